// round 10
// baseline (speedup 1.0000x reference)
#include <cuda_runtime.h>
#include <cuda_fp16.h>
#include <math.h>
#include <stdint.h>

#define BB 2
#define LL 2048
#define DD 2048
#define HV 32
#define HK 16
#define DK 128
#define DV 128
#define KCONV 4
#define KEY_DIM 2048
#define VAL_DIM 4096
#define CONV_DIM 8192
#define BL (BB*LL)

// fp32 intermediates
__device__ float g_mixed[(size_t)BL * CONV_DIM];
__device__ float g_conv [(size_t)BL * CONV_DIM];
__device__ float g_z    [(size_t)BL * VAL_DIM];
__device__ float g_core [(size_t)BL * VAL_DIM];
__device__ float g_gvals[(size_t)BL * HV];
__device__ float g_beta [(size_t)BL * HV];
// fp16 operands
__device__ __half g_hsh   [(size_t)BL * DD];
__device__ __half g_wqkvh [(size_t)CONV_DIM * DD];   // [N][K]
__device__ __half g_wzh   [(size_t)VAL_DIM * DD];    // [N][K]
__device__ __half g_wouth [(size_t)DD * VAL_DIM];    // [N][K]
__device__ __half g_gatedh[(size_t)BL * VAL_DIM];

// ---------------------------------------------------------------------------
// helpers
// ---------------------------------------------------------------------------
__device__ __forceinline__ uint32_t smem_u32(const void* p) {
    uint32_t a;
    asm("{ .reg .u64 t; cvta.to.shared.u64 t, %1; cvt.u32.u64 %0, t; }"
        : "=r"(a) : "l"(p));
    return a;
}
__device__ __forceinline__ void cpa16(uint32_t dst, const void* src) {
    asm volatile("cp.async.cg.shared.global [%0], [%1], 16;\n" :: "r"(dst), "l"(src));
}
#define CP_COMMIT()  asm volatile("cp.async.commit_group;\n")

// ---------------------------------------------------------------------------
// fp16 tensor-core GEMM, ldmatrix + 4-stage cp.async.
// C[M,N] = A[M,K] @ Bt[N,K]^T ; A,Bt fp16 row-major, C fp32.
// CTA tile 128x256, BK=32 halves/stage, 8 warps of 64x64, m16n8k16.
// M%128==0, N%256==0, K%32==0. 256 threads, 1 CTA/SM.
// ---------------------------------------------------------------------------
#define NSTG 4
#define ROWB 80                      // bytes per smem row: 64B data + 16B pad
#define A_BYTES (128 * ROWB)         // 10240
#define B_BYTES (256 * ROWB)         // 20480
#define STG_BYTES (A_BYTES + B_BYTES)
#define GEMM_SMEM (NSTG * STG_BYTES) // 122880

__global__ __launch_bounds__(256, 1) void gemm_f16(
    const __half* __restrict__ A, const __half* __restrict__ Bt,
    float* __restrict__ C, int M, int N, int K)
{
    extern __shared__ char sm[];
    const uint32_t smb = smem_u32(sm);

    const int tid  = threadIdx.x;
    const int warp = tid >> 5;
    const int lane = tid & 31;
    const int g    = lane >> 2;
    const int t    = lane & 3;

    const int wm = (warp >> 2) * 64;   // 0 / 64
    const int wn = (warp & 3)  * 64;   // 0..192

    const __half* Ab = A  + (size_t)blockIdx.y * 128 * K;
    const __half* Bb = Bt + (size_t)blockIdx.x * 256 * K;

    // ldmatrix per-lane byte offsets within a stage
    const uint32_t aOff = (uint32_t)((wm + (lane & 7) + ((lane >> 3) & 1) * 8) * ROWB
                                     + (lane >> 4) * 16);
    const uint32_t bOff = (uint32_t)(A_BYTES
                                     + (wn + (lane & 7) + (lane >> 4) * 8) * ROWB
                                     + ((lane >> 3) & 1) * 16);

    float acc[4][8][4];
    #pragma unroll
    for (int mi = 0; mi < 4; mi++)
        #pragma unroll
        for (int ni = 0; ni < 8; ni++)
            #pragma unroll
            for (int r = 0; r < 4; r++) acc[mi][ni][r] = 0.f;

    const int nt = K >> 5;

    // stage loader: A 512 chunks (2/thread), B 1024 chunks (4/thread)
    #define LOAD_STAGE(KT, STG) do {                                           \
        const int k0_ = (KT) << 5;                                             \
        const uint32_t sa_ = smb + (uint32_t)(STG) * STG_BYTES;                \
        const uint32_t sb_ = sa_ + A_BYTES;                                    \
        _Pragma("unroll")                                                      \
        for (int i_ = 0; i_ < 2; i_++) {                                       \
            const int idx_ = tid + i_ * 256;                                   \
            const int r_ = idx_ >> 2, ch_ = idx_ & 3;                          \
            cpa16(sa_ + (uint32_t)(r_ * ROWB + ch_ * 16),                      \
                  Ab + (size_t)r_ * K + k0_ + ch_ * 8);                        \
        }                                                                      \
        _Pragma("unroll")                                                      \
        for (int i_ = 0; i_ < 4; i_++) {                                       \
            const int idx_ = tid + i_ * 256;                                   \
            const int r_ = idx_ >> 2, ch_ = idx_ & 3;                          \
            cpa16(sb_ + (uint32_t)(r_ * ROWB + ch_ * 16),                      \
                  Bb + (size_t)r_ * K + k0_ + ch_ * 8);                        \
        }                                                                      \
    } while (0)

    // prologue: stages 0..NSTG-2
    #pragma unroll
    for (int s = 0; s < NSTG - 1; s++) {
        if (s < nt) LOAD_STAGE(s, s);
        CP_COMMIT();
    }

    for (int kt = 0; kt < nt; kt++) {
        asm volatile("cp.async.wait_group %0;\n" :: "n"(NSTG - 2));
        __syncthreads();

        const int pf = kt + NSTG - 1;
        if (pf < nt) LOAD_STAGE(pf, pf % NSTG);
        CP_COMMIT();

        const uint32_t sbase = smb + (uint32_t)(kt % NSTG) * STG_BYTES;

        #pragma unroll
        for (int ks = 0; ks < 2; ks++) {
            uint32_t af[4][4], bf[8][2];
            #pragma unroll
            for (int mi = 0; mi < 4; mi++) {
                const uint32_t addr = sbase + aOff + (uint32_t)(mi * 16 * ROWB + ks * 32);
                asm volatile(
                    "ldmatrix.sync.aligned.m8n8.x4.shared.b16 {%0,%1,%2,%3}, [%4];"
                    : "=r"(af[mi][0]), "=r"(af[mi][1]), "=r"(af[mi][2]), "=r"(af[mi][3])
                    : "r"(addr));
            }
            #pragma unroll
            for (int pr = 0; pr < 4; pr++) {
                const uint32_t addr = sbase + bOff + (uint32_t)(pr * 16 * ROWB + ks * 32);
                asm volatile(
                    "ldmatrix.sync.aligned.m8n8.x4.shared.b16 {%0,%1,%2,%3}, [%4];"
                    : "=r"(bf[2*pr][0]), "=r"(bf[2*pr][1]),
                      "=r"(bf[2*pr+1][0]), "=r"(bf[2*pr+1][1])
                    : "r"(addr));
            }
            #pragma unroll
            for (int mi = 0; mi < 4; mi++)
                #pragma unroll
                for (int ni = 0; ni < 8; ni++) {
                    asm volatile(
                        "mma.sync.aligned.m16n8k16.row.col.f32.f16.f16.f32 "
                        "{%0,%1,%2,%3}, {%4,%5,%6,%7}, {%8,%9}, {%0,%1,%2,%3};"
                        : "+f"(acc[mi][ni][0]), "+f"(acc[mi][ni][1]),
                          "+f"(acc[mi][ni][2]), "+f"(acc[mi][ni][3])
                        : "r"(af[mi][0]), "r"(af[mi][1]), "r"(af[mi][2]), "r"(af[mi][3]),
                          "r"(bf[ni][0]), "r"(bf[ni][1]));
                }
        }
    }

    // epilogue
    float* Cblk = C + (size_t)(blockIdx.y * 128) * N + (size_t)blockIdx.x * 256;
    #pragma unroll
    for (int mi = 0; mi < 4; mi++) {
        #pragma unroll
        for (int ni = 0; ni < 8; ni++) {
            const size_t rr = (size_t)(wm + mi * 16 + g);
            const size_t cc = (size_t)(wn + ni * 8 + 2 * t);
            float2 v0 = make_float2(acc[mi][ni][0], acc[mi][ni][1]);
            float2 v1 = make_float2(acc[mi][ni][2], acc[mi][ni][3]);
            *(float2*)&Cblk[rr * N + cc]       = v0;
            *(float2*)&Cblk[(rr + 8) * N + cc] = v1;
        }
    }
    #undef LOAD_STAGE
}

// ---------------------------------------------------------------------------
// fp32 -> fp16 elementwise (n % 4 == 0)
// ---------------------------------------------------------------------------
__global__ __launch_bounds__(256) void f2h_kernel(
    const float* __restrict__ src, __half* __restrict__ dst, int n4)
{
    int i = blockIdx.x * 256 + threadIdx.x;
    if (i >= n4) return;
    float4 v = ((const float4*)src)[i];
    __half2 h0 = __floats2half2_rn(v.x, v.y);
    __half2 h1 = __floats2half2_rn(v.z, v.w);
    uint2 u;
    u.x = *(uint32_t*)&h0;
    u.y = *(uint32_t*)&h1;
    ((uint2*)dst)[i] = u;
}

// ---------------------------------------------------------------------------
// fp32 [R][Nc] -> fp16 transposed [Nc][R]; R,Nc % 32 == 0
// ---------------------------------------------------------------------------
__global__ __launch_bounds__(256) void transpose_f2h(
    const float* __restrict__ src, __half* __restrict__ dst, int R, int Nc)
{
    __shared__ float tile[32][33];
    const int x  = blockIdx.x * 32 + threadIdx.x;
    const int y0 = blockIdx.y * 32 + threadIdx.y;
    #pragma unroll
    for (int j = 0; j < 4; j++)
        tile[threadIdx.y + j * 8][threadIdx.x] = src[(size_t)(y0 + j * 8) * Nc + x];
    __syncthreads();
    const int nx  = blockIdx.y * 32 + threadIdx.x;
    const int ny0 = blockIdx.x * 32 + threadIdx.y;
    #pragma unroll
    for (int j = 0; j < 4; j++)
        dst[(size_t)(ny0 + j * 8) * R + nx] =
            __float2half_rn(tile[threadIdx.x][threadIdx.y + j * 8]);
}

// ---------------------------------------------------------------------------
// beta / g projections + activations
// ---------------------------------------------------------------------------
__global__ __launch_bounds__(128) void bg_kernel(
    const float* __restrict__ hs, const float* __restrict__ W_b,
    const float* __restrict__ W_a, const float* __restrict__ dt_bias,
    const float* __restrict__ A_log)
{
    __shared__ float row[DD];
    const int bl  = blockIdx.x;
    const int tid = threadIdx.x;

    for (int i = tid; i < DD; i += 128)
        row[i] = hs[(size_t)bl * DD + i];
    __syncthreads();

    if (tid < 64) {
        const int h = tid & 31;
        const bool isA = tid >= 32;
        const float* W = isA ? W_a : W_b;
        float acc = 0.f;
        #pragma unroll 8
        for (int i = 0; i < DD; i++)
            acc = fmaf(row[i], W[i * HV + h], acc);
        if (isA) {
            float x  = acc + dt_bias[h];
            float sp = (x > 20.f) ? x : log1pf(expf(x));
            g_gvals[(size_t)bl * HV + h] = -expf(A_log[h]) * sp;
        } else {
            g_beta[(size_t)bl * HV + h] = 1.f / (1.f + expf(-acc));
        }
    }
}

// ---------------------------------------------------------------------------
// causal depthwise conv(K=4) + SiLU + l2norm(q,k) + q*DK^-0.5
// ---------------------------------------------------------------------------
__global__ __launch_bounds__(128) void conv_kernel(const float* __restrict__ conv_w)
{
    const int grp = blockIdx.x;
    const int bl  = blockIdx.y;
    const int l   = bl & (LL - 1);
    const int tid = threadIdx.x;
    const int c   = grp * 128 + tid;

    const float w0 = conv_w[c * 4 + 0];
    const float w1 = conv_w[c * 4 + 1];
    const float w2 = conv_w[c * 4 + 2];
    const float w3 = conv_w[c * 4 + 3];

    const size_t base = (size_t)bl * CONV_DIM + c;
    float acc = g_mixed[base] * w3;
    if (l >= 1) acc = fmaf(g_mixed[base - 1 * CONV_DIM], w2, acc);
    if (l >= 2) acc = fmaf(g_mixed[base - 2 * CONV_DIM], w1, acc);
    if (l >= 3) acc = fmaf(g_mixed[base - 3 * CONV_DIM], w0, acc);

    float s = acc / (1.f + expf(-acc));

    if (grp < 32) {
        __shared__ float red[4];
        float ss = s * s;
        #pragma unroll
        for (int o = 16; o; o >>= 1)
            ss += __shfl_xor_sync(0xffffffffu, ss, o);
        if ((tid & 31) == 0) red[tid >> 5] = ss;
        __syncthreads();
        float tot = red[0] + red[1] + red[2] + red[3];
        s *= rsqrtf(tot + 1e-6f);
        if (grp < 16) s *= 0.08838834764831845f;
    }
    g_conv[base] = s;
}

// ---------------------------------------------------------------------------
// Gated delta-rule scan v2: grid (HV, BB, 2). Block handles one DV-half (64
// cols); 128 threads = 64 cols x 2-way k-split; partials combined via smem.
// ---------------------------------------------------------------------------
__global__ __launch_bounds__(128) void scan_kernel()
{
    const int h    = blockIdx.x;
    const int b    = blockIdx.y;
    const int half = blockIdx.z;
    const int tid  = threadIdx.x;
    const int col  = tid & 63;
    const int kh   = tid >> 6;
    const int hk   = h >> 1;

    __shared__ float ksm[128];
    __shared__ float qsm[128];
    __shared__ float pkv[2][64];
    __shared__ float po [2][64];

    float S[64];
    #pragma unroll
    for (int i = 0; i < 64; i++) S[i] = 0.f;

    const size_t rowbase = (size_t)b * LL * CONV_DIM;
    const int qc = hk * 128 + tid;
    const int kc = KEY_DIM + hk * 128 + tid;
    const int vc = 2 * KEY_DIM + h * 128 + half * 64 + col;

    for (int t = 0; t < LL; t++) {
        const size_t off = rowbase + (size_t)t * CONV_DIM;
        ksm[tid] = g_conv[off + kc];
        qsm[tid] = g_conv[off + qc];
        const float vt = g_conv[off + vc];
        const int sidx = (b * LL + t) * HV + h;
        const float gt = g_gvals[sidx];
        const float bt = g_beta[sidx];
        __syncthreads();

        const float eg = expf(gt);
        const float* kp = ksm + kh * 64;
        const float* qp = qsm + kh * 64;

        float kv = 0.f;
        #pragma unroll
        for (int j = 0; j < 64; j++) {
            S[j] *= eg;
            kv = fmaf(kp[j], S[j], kv);
        }
        pkv[kh][col] = kv;
        __syncthreads();

        const float delta = (vt - pkv[0][col] - pkv[1][col]) * bt;

        float o = 0.f;
        #pragma unroll
        for (int j = 0; j < 64; j++) {
            S[j] = fmaf(kp[j], delta, S[j]);
            o = fmaf(qp[j], S[j], o);
        }
        po[kh][col] = o;
        __syncthreads();

        if (kh == 0)
            g_core[((size_t)(b * LL + t)) * VAL_DIM + h * 128 + half * 64 + col]
                = po[0][col] + po[1][col];
    }
}

// ---------------------------------------------------------------------------
// Gated RMSNorm -> fp16 output for final GEMM
// ---------------------------------------------------------------------------
__global__ __launch_bounds__(128) void gatednorm_kernel(const float* __restrict__ norm_w)
{
    const int h   = blockIdx.x;
    const int bl  = blockIdx.y;
    const int tid = threadIdx.x;
    const size_t idx = (size_t)bl * VAL_DIM + h * 128 + tid;

    float c  = g_core[idx];
    float zz = g_z[idx];
    float gz = zz / (1.f + expf(-zz));
    float x  = c * gz;

    __shared__ float red[4];
    float ss = x * x;
    #pragma unroll
    for (int o = 16; o; o >>= 1)
        ss += __shfl_xor_sync(0xffffffffu, ss, o);
    if ((tid & 31) == 0) red[tid >> 5] = ss;
    __syncthreads();
    float tot  = red[0] + red[1] + red[2] + red[3];
    float mean = tot * (1.f / 128.f);

    g_gatedh[idx] = __float2half_rn(x * rsqrtf(mean + 1e-6f) * norm_w[tid]);
}

// ---------------------------------------------------------------------------
extern "C" void kernel_launch(void* const* d_in, const int* in_sizes, int n_in,
                              void* d_out, int out_size)
{
    const float* hs      = (const float*)d_in[0];
    const float* W_qkv   = (const float*)d_in[1];
    const float* W_z     = (const float*)d_in[2];
    const float* W_b     = (const float*)d_in[3];
    const float* W_a     = (const float*)d_in[4];
    const float* conv_w  = (const float*)d_in[5];
    const float* dt_bias = (const float*)d_in[6];
    const float* A_log   = (const float*)d_in[7];
    const float* norm_w  = (const float*)d_in[8];
    const float* W_out   = (const float*)d_in[9];
    float* out = (float*)d_out;

    float*  mixed_ptr; cudaGetSymbolAddress((void**)&mixed_ptr, g_mixed);
    float*  z_ptr;     cudaGetSymbolAddress((void**)&z_ptr,     g_z);
    __half* hsh;       cudaGetSymbolAddress((void**)&hsh,       g_hsh);
    __half* wqkvh;     cudaGetSymbolAddress((void**)&wqkvh,     g_wqkvh);
    __half* wzh;       cudaGetSymbolAddress((void**)&wzh,       g_wzh);
    __half* wouth;     cudaGetSymbolAddress((void**)&wouth,     g_wouth);
    __half* gatedh;    cudaGetSymbolAddress((void**)&gatedh,    g_gatedh);

    cudaFuncSetAttribute(gemm_f16,
        cudaFuncAttributeMaxDynamicSharedMemorySize, GEMM_SMEM);

    // fp16 conversions (+ weight transposes to [N][K])
    f2h_kernel<<<(BL * DD / 4 + 255) / 256, 256>>>(hs, hsh, BL * DD / 4);
    transpose_f2h<<<dim3(CONV_DIM / 32, DD / 32), dim3(32, 8)>>>(W_qkv, wqkvh, DD, CONV_DIM);
    transpose_f2h<<<dim3(VAL_DIM / 32, DD / 32), dim3(32, 8)>>>(W_z, wzh, DD, VAL_DIM);
    transpose_f2h<<<dim3(DD / 32, VAL_DIM / 32), dim3(32, 8)>>>(W_out, wouth, VAL_DIM, DD);

    gemm_f16<<<dim3(CONV_DIM/256, BL/128), 256, GEMM_SMEM>>>(hsh, wqkvh, mixed_ptr, BL, CONV_DIM, DD);
    gemm_f16<<<dim3(VAL_DIM/256, BL/128), 256, GEMM_SMEM>>>(hsh, wzh, z_ptr, BL, VAL_DIM, DD);
    bg_kernel<<<BL, 128>>>(hs, W_b, W_a, dt_bias, A_log);
    conv_kernel<<<dim3(CONV_DIM/128, BL), 128>>>(conv_w);
    scan_kernel<<<dim3(HV, BB, 2), 128>>>();
    gatednorm_kernel<<<dim3(HV, BL), 128>>>(norm_w);
    gemm_f16<<<dim3(DD/256, BL/128), 256, GEMM_SMEM>>>(gatedh, wouth, out, BL, DD, VAL_DIM);
}

// round 11
// speedup vs baseline: 1.2881x; 1.2881x over previous
#include <cuda_runtime.h>
#include <cuda_fp16.h>
#include <math.h>
#include <stdint.h>

#define BB 2
#define LL 2048
#define DD 2048
#define HV 32
#define HK 16
#define DK 128
#define DV 128
#define KCONV 4
#define KEY_DIM 2048
#define VAL_DIM 4096
#define CONV_DIM 8192
#define BL (BB*LL)

// fp32 intermediates
__device__ float g_mixed[(size_t)BL * CONV_DIM];
__device__ float g_conv [(size_t)BL * CONV_DIM];
__device__ float g_z    [(size_t)BL * VAL_DIM];
__device__ float g_core [(size_t)BL * VAL_DIM];
__device__ float g_gvals[(size_t)BL * HV];
__device__ float g_beta [(size_t)BL * HV];
// fp16 operands
__device__ __half g_hsh   [(size_t)BL * DD];
__device__ __half g_wqkvh [(size_t)CONV_DIM * DD];   // [N][K]
__device__ __half g_wzh   [(size_t)VAL_DIM * DD];    // [N][K]
__device__ __half g_wouth [(size_t)DD * VAL_DIM];    // [N][K]
__device__ __half g_gatedh[(size_t)BL * VAL_DIM];

// ---------------------------------------------------------------------------
// helpers
// ---------------------------------------------------------------------------
__device__ __forceinline__ uint32_t smem_u32(const void* p) {
    uint32_t a;
    asm("{ .reg .u64 t; cvta.to.shared.u64 t, %1; cvt.u32.u64 %0, t; }"
        : "=r"(a) : "l"(p));
    return a;
}
__device__ __forceinline__ void cpa16(uint32_t dst, const void* src) {
    asm volatile("cp.async.cg.shared.global [%0], [%1], 16;\n" :: "r"(dst), "l"(src));
}
#define CP_COMMIT()  asm volatile("cp.async.commit_group;\n")

// ---------------------------------------------------------------------------
// fp16 tensor-core GEMM, ldmatrix + 4-stage cp.async.
// C[M,N] = A[M,K] @ Bt[N,K]^T ; A,Bt fp16 row-major, C fp32.
// CTA tile 128x256, BK=32 halves/stage, 8 warps of 64x64, m16n8k16.
// ---------------------------------------------------------------------------
#define NSTG 4
#define ROWB 80                      // bytes per smem row: 64B data + 16B pad
#define A_BYTES (128 * ROWB)
#define B_BYTES (256 * ROWB)
#define STG_BYTES (A_BYTES + B_BYTES)
#define GEMM_SMEM (NSTG * STG_BYTES) // 122880

__global__ __launch_bounds__(256, 1) void gemm_f16(
    const __half* __restrict__ A, const __half* __restrict__ Bt,
    float* __restrict__ C, int M, int N, int K)
{
    extern __shared__ char sm[];
    const uint32_t smb = smem_u32(sm);

    const int tid  = threadIdx.x;
    const int warp = tid >> 5;
    const int lane = tid & 31;
    const int g    = lane >> 2;
    const int t    = lane & 3;

    const int wm = (warp >> 2) * 64;
    const int wn = (warp & 3)  * 64;

    const __half* Ab = A  + (size_t)blockIdx.y * 128 * K;
    const __half* Bb = Bt + (size_t)blockIdx.x * 256 * K;

    const uint32_t aOff = (uint32_t)((wm + (lane & 7) + ((lane >> 3) & 1) * 8) * ROWB
                                     + (lane >> 4) * 16);
    const uint32_t bOff = (uint32_t)(A_BYTES
                                     + (wn + (lane & 7) + (lane >> 4) * 8) * ROWB
                                     + ((lane >> 3) & 1) * 16);

    float acc[4][8][4];
    #pragma unroll
    for (int mi = 0; mi < 4; mi++)
        #pragma unroll
        for (int ni = 0; ni < 8; ni++)
            #pragma unroll
            for (int r = 0; r < 4; r++) acc[mi][ni][r] = 0.f;

    const int nt = K >> 5;

    #define LOAD_STAGE(KT, STG) do {                                           \
        const int k0_ = (KT) << 5;                                             \
        const uint32_t sa_ = smb + (uint32_t)(STG) * STG_BYTES;                \
        const uint32_t sb_ = sa_ + A_BYTES;                                    \
        _Pragma("unroll")                                                      \
        for (int i_ = 0; i_ < 2; i_++) {                                       \
            const int idx_ = tid + i_ * 256;                                   \
            const int r_ = idx_ >> 2, ch_ = idx_ & 3;                          \
            cpa16(sa_ + (uint32_t)(r_ * ROWB + ch_ * 16),                      \
                  Ab + (size_t)r_ * K + k0_ + ch_ * 8);                        \
        }                                                                      \
        _Pragma("unroll")                                                      \
        for (int i_ = 0; i_ < 4; i_++) {                                       \
            const int idx_ = tid + i_ * 256;                                   \
            const int r_ = idx_ >> 2, ch_ = idx_ & 3;                          \
            cpa16(sb_ + (uint32_t)(r_ * ROWB + ch_ * 16),                      \
                  Bb + (size_t)r_ * K + k0_ + ch_ * 8);                        \
        }                                                                      \
    } while (0)

    #pragma unroll
    for (int s = 0; s < NSTG - 1; s++) {
        if (s < nt) LOAD_STAGE(s, s);
        CP_COMMIT();
    }

    for (int kt = 0; kt < nt; kt++) {
        asm volatile("cp.async.wait_group %0;\n" :: "n"(NSTG - 2));
        __syncthreads();

        const int pf = kt + NSTG - 1;
        if (pf < nt) LOAD_STAGE(pf, pf % NSTG);
        CP_COMMIT();

        const uint32_t sbase = smb + (uint32_t)(kt % NSTG) * STG_BYTES;

        #pragma unroll
        for (int ks = 0; ks < 2; ks++) {
            uint32_t af[4][4], bf[8][2];
            #pragma unroll
            for (int mi = 0; mi < 4; mi++) {
                const uint32_t addr = sbase + aOff + (uint32_t)(mi * 16 * ROWB + ks * 32);
                asm volatile(
                    "ldmatrix.sync.aligned.m8n8.x4.shared.b16 {%0,%1,%2,%3}, [%4];"
                    : "=r"(af[mi][0]), "=r"(af[mi][1]), "=r"(af[mi][2]), "=r"(af[mi][3])
                    : "r"(addr));
            }
            #pragma unroll
            for (int pr = 0; pr < 4; pr++) {
                const uint32_t addr = sbase + bOff + (uint32_t)(pr * 16 * ROWB + ks * 32);
                asm volatile(
                    "ldmatrix.sync.aligned.m8n8.x4.shared.b16 {%0,%1,%2,%3}, [%4];"
                    : "=r"(bf[2*pr][0]), "=r"(bf[2*pr][1]),
                      "=r"(bf[2*pr+1][0]), "=r"(bf[2*pr+1][1])
                    : "r"(addr));
            }
            #pragma unroll
            for (int mi = 0; mi < 4; mi++)
                #pragma unroll
                for (int ni = 0; ni < 8; ni++) {
                    asm volatile(
                        "mma.sync.aligned.m16n8k16.row.col.f32.f16.f16.f32 "
                        "{%0,%1,%2,%3}, {%4,%5,%6,%7}, {%8,%9}, {%0,%1,%2,%3};"
                        : "+f"(acc[mi][ni][0]), "+f"(acc[mi][ni][1]),
                          "+f"(acc[mi][ni][2]), "+f"(acc[mi][ni][3])
                        : "r"(af[mi][0]), "r"(af[mi][1]), "r"(af[mi][2]), "r"(af[mi][3]),
                          "r"(bf[ni][0]), "r"(bf[ni][1]));
                }
        }
    }

    float* Cblk = C + (size_t)(blockIdx.y * 128) * N + (size_t)blockIdx.x * 256;
    #pragma unroll
    for (int mi = 0; mi < 4; mi++) {
        #pragma unroll
        for (int ni = 0; ni < 8; ni++) {
            const size_t rr = (size_t)(wm + mi * 16 + g);
            const size_t cc = (size_t)(wn + ni * 8 + 2 * t);
            float2 v0 = make_float2(acc[mi][ni][0], acc[mi][ni][1]);
            float2 v1 = make_float2(acc[mi][ni][2], acc[mi][ni][3]);
            *(float2*)&Cblk[rr * N + cc]       = v0;
            *(float2*)&Cblk[(rr + 8) * N + cc] = v1;
        }
    }
    #undef LOAD_STAGE
}

// ---------------------------------------------------------------------------
// fp32 -> fp16 elementwise (n % 4 == 0)
// ---------------------------------------------------------------------------
__global__ __launch_bounds__(256) void f2h_kernel(
    const float* __restrict__ src, __half* __restrict__ dst, int n4)
{
    int i = blockIdx.x * 256 + threadIdx.x;
    if (i >= n4) return;
    float4 v = ((const float4*)src)[i];
    __half2 h0 = __floats2half2_rn(v.x, v.y);
    __half2 h1 = __floats2half2_rn(v.z, v.w);
    uint2 u;
    u.x = *(uint32_t*)&h0;
    u.y = *(uint32_t*)&h1;
    ((uint2*)dst)[i] = u;
}

// ---------------------------------------------------------------------------
// fp32 [R][Nc] -> fp16 transposed [Nc][R]; R,Nc % 32 == 0
// ---------------------------------------------------------------------------
__global__ __launch_bounds__(256) void transpose_f2h(
    const float* __restrict__ src, __half* __restrict__ dst, int R, int Nc)
{
    __shared__ float tile[32][33];
    const int x  = blockIdx.x * 32 + threadIdx.x;
    const int y0 = blockIdx.y * 32 + threadIdx.y;
    #pragma unroll
    for (int j = 0; j < 4; j++)
        tile[threadIdx.y + j * 8][threadIdx.x] = src[(size_t)(y0 + j * 8) * Nc + x];
    __syncthreads();
    const int nx  = blockIdx.y * 32 + threadIdx.x;
    const int ny0 = blockIdx.x * 32 + threadIdx.y;
    #pragma unroll
    for (int j = 0; j < 4; j++)
        dst[(size_t)(ny0 + j * 8) * R + nx] =
            __float2half_rn(tile[threadIdx.x][threadIdx.y + j * 8]);
}

// ---------------------------------------------------------------------------
// beta / g projections + activations
// ---------------------------------------------------------------------------
__global__ __launch_bounds__(128) void bg_kernel(
    const float* __restrict__ hs, const float* __restrict__ W_b,
    const float* __restrict__ W_a, const float* __restrict__ dt_bias,
    const float* __restrict__ A_log)
{
    __shared__ float row[DD];
    const int bl  = blockIdx.x;
    const int tid = threadIdx.x;

    for (int i = tid; i < DD; i += 128)
        row[i] = hs[(size_t)bl * DD + i];
    __syncthreads();

    if (tid < 64) {
        const int h = tid & 31;
        const bool isA = tid >= 32;
        const float* W = isA ? W_a : W_b;
        float acc = 0.f;
        #pragma unroll 8
        for (int i = 0; i < DD; i++)
            acc = fmaf(row[i], W[i * HV + h], acc);
        if (isA) {
            float x  = acc + dt_bias[h];
            float sp = (x > 20.f) ? x : log1pf(expf(x));
            g_gvals[(size_t)bl * HV + h] = -expf(A_log[h]) * sp;
        } else {
            g_beta[(size_t)bl * HV + h] = 1.f / (1.f + expf(-acc));
        }
    }
}

// ---------------------------------------------------------------------------
// causal depthwise conv(K=4) + SiLU + l2norm(q,k) + q*DK^-0.5
// ---------------------------------------------------------------------------
__global__ __launch_bounds__(128) void conv_kernel(const float* __restrict__ conv_w)
{
    const int grp = blockIdx.x;
    const int bl  = blockIdx.y;
    const int l   = bl & (LL - 1);
    const int tid = threadIdx.x;
    const int c   = grp * 128 + tid;

    const float w0 = conv_w[c * 4 + 0];
    const float w1 = conv_w[c * 4 + 1];
    const float w2 = conv_w[c * 4 + 2];
    const float w3 = conv_w[c * 4 + 3];

    const size_t base = (size_t)bl * CONV_DIM + c;
    float acc = g_mixed[base] * w3;
    if (l >= 1) acc = fmaf(g_mixed[base - 1 * CONV_DIM], w2, acc);
    if (l >= 2) acc = fmaf(g_mixed[base - 2 * CONV_DIM], w1, acc);
    if (l >= 3) acc = fmaf(g_mixed[base - 3 * CONV_DIM], w0, acc);

    float s = acc / (1.f + expf(-acc));

    if (grp < 32) {
        __shared__ float red[4];
        float ss = s * s;
        #pragma unroll
        for (int o = 16; o; o >>= 1)
            ss += __shfl_xor_sync(0xffffffffu, ss, o);
        if ((tid & 31) == 0) red[tid >> 5] = ss;
        __syncthreads();
        float tot = red[0] + red[1] + red[2] + red[3];
        s *= rsqrtf(tot + 1e-6f);
        if (grp < 16) s *= 0.08838834764831845f;
    }
    g_conv[base] = s;
}

// ---------------------------------------------------------------------------
// Gated delta-rule scan v3: grid (HV, BB, 2), 128 thr = 64 cols x 2 k-split.
// Software-prefetches t+1's k/q/v/g/beta into registers during step t so the
// global-load latency is off the sequential critical path.
// ---------------------------------------------------------------------------
__global__ __launch_bounds__(128) void scan_kernel()
{
    const int h    = blockIdx.x;
    const int b    = blockIdx.y;
    const int half = blockIdx.z;
    const int tid  = threadIdx.x;
    const int col  = tid & 63;
    const int kh   = tid >> 6;
    const int hk   = h >> 1;

    __shared__ float ksm[128];
    __shared__ float qsm[128];
    __shared__ float pkv[2][64];
    __shared__ float po [2][64];

    float S[64];
    #pragma unroll
    for (int i = 0; i < 64; i++) S[i] = 0.f;

    const size_t rowbase = (size_t)b * LL * CONV_DIM;
    const int qc = hk * 128 + tid;
    const int kc = KEY_DIM + hk * 128 + tid;
    const int vc = 2 * KEY_DIM + h * 128 + half * 64 + col;

    // preload t = 0
    float kn = g_conv[rowbase + kc];
    float qn = g_conv[rowbase + qc];
    float vn = g_conv[rowbase + vc];
    float gn = g_gvals[(size_t)(b * LL) * HV + h];
    float bn = g_beta [(size_t)(b * LL) * HV + h];

    for (int t = 0; t < LL; t++) {
        ksm[tid] = kn;
        qsm[tid] = qn;
        const float vt = vn, gt = gn, bt = bn;
        __syncthreads();

        // prefetch t+1 (hidden behind this step's compute)
        if (t + 1 < LL) {
            const size_t offn = rowbase + (size_t)(t + 1) * CONV_DIM;
            kn = g_conv[offn + kc];
            qn = g_conv[offn + qc];
            vn = g_conv[offn + vc];
            const int sidx = (b * LL + t + 1) * HV + h;
            gn = g_gvals[sidx];
            bn = g_beta[sidx];
        }

        const float eg = expf(gt);
        const float* kp = ksm + kh * 64;
        const float* qp = qsm + kh * 64;

        float kv = 0.f;
        #pragma unroll
        for (int j = 0; j < 64; j++) {
            S[j] *= eg;
            kv = fmaf(kp[j], S[j], kv);
        }
        pkv[kh][col] = kv;
        __syncthreads();

        const float delta = (vt - pkv[0][col] - pkv[1][col]) * bt;

        float o = 0.f;
        #pragma unroll
        for (int j = 0; j < 64; j++) {
            S[j] = fmaf(kp[j], delta, S[j]);
            o = fmaf(qp[j], S[j], o);
        }
        po[kh][col] = o;
        __syncthreads();

        if (kh == 0)
            g_core[((size_t)(b * LL + t)) * VAL_DIM + h * 128 + half * 64 + col]
                = po[0][col] + po[1][col];
    }
}

// ---------------------------------------------------------------------------
// Gated RMSNorm -> fp16 output for final GEMM
// ---------------------------------------------------------------------------
__global__ __launch_bounds__(128) void gatednorm_kernel(const float* __restrict__ norm_w)
{
    const int h   = blockIdx.x;
    const int bl  = blockIdx.y;
    const int tid = threadIdx.x;
    const size_t idx = (size_t)bl * VAL_DIM + h * 128 + tid;

    float c  = g_core[idx];
    float zz = g_z[idx];
    float gz = zz / (1.f + expf(-zz));
    float x  = c * gz;

    __shared__ float red[4];
    float ss = x * x;
    #pragma unroll
    for (int o = 16; o; o >>= 1)
        ss += __shfl_xor_sync(0xffffffffu, ss, o);
    if ((tid & 31) == 0) red[tid >> 5] = ss;
    __syncthreads();
    float tot  = red[0] + red[1] + red[2] + red[3];
    float mean = tot * (1.f / 128.f);

    g_gatedh[idx] = __float2half_rn(x * rsqrtf(mean + 1e-6f) * norm_w[tid]);
}

// ---------------------------------------------------------------------------
extern "C" void kernel_launch(void* const* d_in, const int* in_sizes, int n_in,
                              void* d_out, int out_size)
{
    const float* hs      = (const float*)d_in[0];
    const float* W_qkv   = (const float*)d_in[1];
    const float* W_z     = (const float*)d_in[2];
    const float* W_b     = (const float*)d_in[3];
    const float* W_a     = (const float*)d_in[4];
    const float* conv_w  = (const float*)d_in[5];
    const float* dt_bias = (const float*)d_in[6];
    const float* A_log   = (const float*)d_in[7];
    const float* norm_w  = (const float*)d_in[8];
    const float* W_out   = (const float*)d_in[9];
    float* out = (float*)d_out;

    float*  mixed_ptr; cudaGetSymbolAddress((void**)&mixed_ptr, g_mixed);
    float*  z_ptr;     cudaGetSymbolAddress((void**)&z_ptr,     g_z);
    __half* hsh;       cudaGetSymbolAddress((void**)&hsh,       g_hsh);
    __half* wqkvh;     cudaGetSymbolAddress((void**)&wqkvh,     g_wqkvh);
    __half* wzh;       cudaGetSymbolAddress((void**)&wzh,       g_wzh);
    __half* wouth;     cudaGetSymbolAddress((void**)&wouth,     g_wouth);
    __half* gatedh;    cudaGetSymbolAddress((void**)&gatedh,    g_gatedh);

    // side stream + events, created once (first call runs outside capture)
    static cudaStream_t s2 = nullptr;
    static cudaEvent_t e0, eBG, eCONV, eG2;
    if (s2 == nullptr) {
        cudaStreamCreateWithFlags(&s2, cudaStreamNonBlocking);
        cudaEventCreateWithFlags(&e0,    cudaEventDisableTiming);
        cudaEventCreateWithFlags(&eBG,   cudaEventDisableTiming);
        cudaEventCreateWithFlags(&eCONV, cudaEventDisableTiming);
        cudaEventCreateWithFlags(&eG2,   cudaEventDisableTiming);
        cudaFuncSetAttribute(gemm_f16,
            cudaFuncAttributeMaxDynamicSharedMemorySize, GEMM_SMEM);
    }

    // fork: side stream handles bg + off-critical transposes, later gemm2
    cudaEventRecord(e0, 0);
    cudaStreamWaitEvent(s2, e0, 0);
    bg_kernel<<<BL, 128, 0, s2>>>(hs, W_b, W_a, dt_bias, A_log);
    cudaEventRecord(eBG, s2);
    transpose_f2h<<<dim3(VAL_DIM / 32, DD / 32), dim3(32, 8), 0, s2>>>(W_z, wzh, DD, VAL_DIM);
    transpose_f2h<<<dim3(DD / 32, VAL_DIM / 32), dim3(32, 8), 0, s2>>>(W_out, wouth, VAL_DIM, DD);

    // main chain (default stream)
    f2h_kernel<<<(BL * DD / 4 + 255) / 256, 256>>>(hs, hsh, BL * DD / 4);
    transpose_f2h<<<dim3(CONV_DIM / 32, DD / 32), dim3(32, 8)>>>(W_qkv, wqkvh, DD, CONV_DIM);
    gemm_f16<<<dim3(CONV_DIM/256, BL/128), 256, GEMM_SMEM>>>(hsh, wqkvh, mixed_ptr, BL, CONV_DIM, DD);
    conv_kernel<<<dim3(CONV_DIM/128, BL), 128>>>(conv_w);
    cudaEventRecord(eCONV, 0);

    // side: gemm2 (z) runs concurrently with the scan
    cudaStreamWaitEvent(s2, eCONV, 0);
    gemm_f16<<<dim3(VAL_DIM/256, BL/128), 256, GEMM_SMEM, s2>>>(hsh, wzh, z_ptr, BL, VAL_DIM, DD);
    cudaEventRecord(eG2, s2);

    // main: scan needs bg results
    cudaStreamWaitEvent(0, eBG, 0);
    scan_kernel<<<dim3(HV, BB, 2), 128>>>();

    // join: gatednorm needs z from side stream
    cudaStreamWaitEvent(0, eG2, 0);
    gatednorm_kernel<<<dim3(HV, BL), 128>>>(norm_w);
    gemm_f16<<<dim3(DD/256, BL/128), 256, GEMM_SMEM>>>(gatedh, wouth, out, BL, DD, VAL_DIM);
}